// round 7
// baseline (speedup 1.0000x reference)
#include <cuda_runtime.h>
#include <cuda_bf16.h>

// ---------------------------------------------------------------------------
// Quanv3x3 9-qubit statevector sim, packed-f32x2.
//
// One warp per sim (25088 sims). 512 amps = 16 complex/lane, stored as
// 8 x f32x2 packed pairs (pair dimension = qubit 7).
//
// Amp index bits:  lane b0=q8  b1=q5  b2=q3  b3=q1  b4=q2
//                  pair-lo/hi = q7;  k b0=q6  k b1=q4  k b2=q0
// Only CRX of pair (3,2) crosses lanes (xor 16). All controlled gates use
// constant-folded controls (identity rotation on off lanes) -> no divergence.
//
// Occupancy note (R5 lesson): natural liveness is ~90 regs. launch_bounds
// must keep the reg ceiling >= 90 or ptxas rematerializes packed constants
// and instruction count blows up ~1.6x. (128,5) -> 96-reg ceiling, 20 warps.
// ---------------------------------------------------------------------------

#define FULLMASK 0xffffffffu
typedef unsigned long long u64;

__device__ float g_s[7200];     // sin(pi * avg)  per (b,row,col)
__device__ float g_c[7200];     // cos(pi * avg)
__device__ float g_gc[64];      // cos(theta/2) per channel (4x16)
__device__ float g_gs[64];      // sin(theta/2)

__global__ void prep_kernel(const float* __restrict__ x,
                            const float* __restrict__ qp,
                            float* __restrict__ out) {
    int i = blockIdx.x * blockDim.x + threadIdx.x;
    if (i < 28800) out[i] = 0.0f;
    if (i < 7200) {
        const float* p = x + i * 3;
        float a = (p[0] + p[1] + p[2]) * (1.0f / 3.0f);
        float sv, cv;
        sincosf(3.14159265358979323846f * a, &sv, &cv);
        g_s[i] = sv;
        g_c[i] = cv;
    }
    if (i < 64) {
        float h = qp[i] * 0.5f;
        g_gc[i] = cosf(h);
        g_gs[i] = sinf(h);
    }
}

// ---- packed f32x2 primitives ----------------------------------------------
__device__ __forceinline__ u64 pk(float lo, float hi) {
    u64 r;
    asm("mov.b64 %0, {%1, %2};" : "=l"(r) : "f"(lo), "f"(hi));
    return r;
}
__device__ __forceinline__ void upk(u64 v, float& lo, float& hi) {
    asm("mov.b64 {%0, %1}, %2;" : "=f"(lo), "=f"(hi) : "l"(v));
}
__device__ __forceinline__ u64 f2fma(u64 a, u64 b, u64 c) {
    u64 d;
    asm("fma.rn.f32x2 %0, %1, %2, %3;" : "=l"(d) : "l"(a), "l"(b), "l"(c));
    return d;
}
__device__ __forceinline__ u64 f2mul(u64 a, u64 b) {
    u64 d;
    asm("mul.rn.f32x2 %0, %1, %2;" : "=l"(d) : "l"(a), "l"(b));
    return d;
}
__device__ __forceinline__ u64 f2swap(u64 v) {
    float lo, hi; upk(v, lo, hi); return pk(hi, lo);
}

// CRZ on one packed pair: nr = ch*r + (-se)*i ; ni = ch*i + se*r
__device__ __forceinline__ void crz1(u64& r, u64& i, u64 ch2, u64 se2, u64 mse2) {
    u64 tr = f2mul(mse2, i);
    u64 ti = f2mul(se2, r);
    r = f2fma(ch2, r, tr);
    i = f2fma(ch2, i, ti);
}

// CRX mixing packed pair A (target bit 0) with packed pair B (target bit 1).
__device__ __forceinline__ void crx2(u64& rA, u64& iA, u64& rB, u64& iB,
                                     u64 ch2, u64 sh2, u64 msh2) {
    u64 m0 = f2mul(sh2,  iB);
    u64 m1 = f2mul(msh2, rB);
    u64 m2 = f2mul(sh2,  iA);
    u64 m3 = f2mul(msh2, rA);
    rA = f2fma(ch2, rA, m0);
    iA = f2fma(ch2, iA, m1);
    rB = f2fma(ch2, rB, m2);
    iB = f2fma(ch2, iB, m3);
}

__global__ __launch_bounds__(128, 5) void sim_kernel(float* __restrict__ out) {
    int gwarp = (blockIdx.x * blockDim.x + threadIdx.x) >> 5;
    int lane = threadIdx.x & 31;

    int b   = gwarp / 3136;
    int rem = gwarp - b * 3136;
    int ch  = rem / 784;
    int pos = rem - ch * 784;
    int r_  = pos / 28;
    int c_  = pos - r_ * 28;

    // ---- patch angles: cq = sin(pi*p), sq = -cos(pi*p)  (precomputed tables)
    float sv = 0.0f, cv = 0.0f;
    if (lane < 9) {
        int dr = lane / 3;
        int dc = lane - dr * 3;
        int idx = b * 900 + (r_ + dr) * 30 + (c_ + dc);
        sv = __ldg(g_s + idx);
        cv = __ldg(g_c + idx);
    }
    float cq[9], sq[9];
#pragma unroll
    for (int q = 0; q < 9; q++) {
        cq[q] = __shfl_sync(FULLMASK, sv, q);
        sq[q] = -__shfl_sync(FULLMASK, cv, q);
    }

    // ---- initial product state: amp(idx) = rr * (-i)^popcount(idx)
    float lr = ((lane & 1)  ? sq[8] : cq[8]) *
               ((lane & 2)  ? sq[5] : cq[5]) *
               ((lane & 4)  ? sq[3] : cq[3]) *
               ((lane & 8)  ? sq[1] : cq[1]) *
               ((lane & 16) ? sq[2] : cq[2]);
    int lk = __popc(lane & 31) & 3;
    float wr = (lk == 0) ? 1.0f : ((lk == 2) ? -1.0f : 0.0f);
    float wi = (lk == 3) ? 1.0f : ((lk == 1) ? -1.0f : 0.0f);

    u64 re[8], im[8];
#pragma unroll
    for (int k = 0; k < 8; k++) {
        float rr = lr * ((k & 1) ? sq[6] : cq[6]) *
                        ((k & 2) ? sq[4] : cq[4]) *
                        ((k & 4) ? sq[0] : cq[0]);
        int p = __popc(k) & 3;  // compile-time under unroll
        float wkr = (p == 0) ? wr : (p == 1) ? wi : (p == 2) ? -wr : -wi;
        float wki = (p == 0) ? wi : (p == 1) ? -wr : (p == 2) ? -wi : wr;
        float t1 = rr * cq[7], t2 = rr * sq[7];
        re[k] = pk(t1 * wkr,  t2 * wki);
        im[k] = pk(t1 * wki, -(t2 * wkr));
    }

    const float* gc = g_gc + ch * 16;
    const float* gs = g_gs + ch * 16;

    // ---- gate 0: (1,0). ctl = lane&8; CRZ sign by k&4; CRX pairs k^4
    {
        bool ctl = (lane & 8) != 0;
        float c = __ldg(gc + 0), s = __ldg(gs + 0);
        float ce = ctl ? c : 1.0f, se = ctl ? s : 0.0f;
        u64 ch2 = pk(ce, ce), sP = pk(se, se), sN = pk(-se, -se);
#pragma unroll
        for (int k = 0; k < 8; k++)
            crz1(re[k], im[k], ch2, (k & 4) ? sP : sN, (k & 4) ? sN : sP);
        float cx = __ldg(gc + 1), sx = __ldg(gs + 1);
        float cxe = ctl ? cx : 1.0f, sxe = ctl ? sx : 0.0f;
        u64 cx2 = pk(cxe, cxe), x2P = pk(sxe, sxe), x2N = pk(-sxe, -sxe);
        crx2(re[0], im[0], re[4], im[4], cx2, x2P, x2N);
        crx2(re[1], im[1], re[5], im[5], cx2, x2P, x2N);
        crx2(re[2], im[2], re[6], im[6], cx2, x2P, x2N);
        crx2(re[3], im[3], re[7], im[7], cx2, x2P, x2N);
    }
    // ---- gate 1: (3,2). ctl = lane&4; CRZ sign by lane&16; CRX cross-lane xor16
    {
        bool ctl = (lane & 4) != 0;
        float c = __ldg(gc + 2), s = __ldg(gs + 2);
        float sgn = (lane & 16) ? s : -s;
        float ce = ctl ? c : 1.0f, se = ctl ? sgn : 0.0f;
        u64 ch2 = pk(ce, ce), sP = pk(se, se), sN = pk(-se, -se);
#pragma unroll
        for (int k = 0; k < 8; k++)
            crz1(re[k], im[k], ch2, sP, sN);
        float cx = __ldg(gc + 3), sx = __ldg(gs + 3);
        float cxe = ctl ? cx : 1.0f, sxe = ctl ? sx : 0.0f;
        u64 cx2 = pk(cxe, cxe), x2P = pk(sxe, sxe), x2N = pk(-sxe, -sxe);
#pragma unroll
        for (int k = 0; k < 8; k++) {
            u64 orr = __shfl_xor_sync(FULLMASK, re[k], 16);
            u64 oii = __shfl_xor_sync(FULLMASK, im[k], 16);
            u64 m0 = f2mul(x2P, oii);
            u64 m1 = f2mul(x2N, orr);
            re[k] = f2fma(cx2, re[k], m0);
            im[k] = f2fma(cx2, im[k], m1);
        }
    }
    // ---- gate 2: (2,0). ctl = lane&16; same shape as gate 0
    {
        bool ctl = (lane & 16) != 0;
        float c = __ldg(gc + 4), s = __ldg(gs + 4);
        float ce = ctl ? c : 1.0f, se = ctl ? s : 0.0f;
        u64 ch2 = pk(ce, ce), sP = pk(se, se), sN = pk(-se, -se);
#pragma unroll
        for (int k = 0; k < 8; k++)
            crz1(re[k], im[k], ch2, (k & 4) ? sP : sN, (k & 4) ? sN : sP);
        float cx = __ldg(gc + 5), sx = __ldg(gs + 5);
        float cxe = ctl ? cx : 1.0f, sxe = ctl ? sx : 0.0f;
        u64 cx2 = pk(cxe, cxe), x2P = pk(sxe, sxe), x2N = pk(-sxe, -sxe);
        crx2(re[0], im[0], re[4], im[4], cx2, x2P, x2N);
        crx2(re[1], im[1], re[5], im[5], cx2, x2P, x2N);
        crx2(re[2], im[2], re[6], im[6], cx2, x2P, x2N);
        crx2(re[3], im[3], re[7], im[7], cx2, x2P, x2N);
    }
    // ---- gate 3: (8,7). ctl = lane&1; target = within-pair bit (q7)
    {
        bool ctl = (lane & 1) != 0;
        float c = __ldg(gc + 6), s = __ldg(gs + 6);
        float ce = ctl ? c : 1.0f, se = ctl ? s : 0.0f;
        u64 ch2 = pk(ce, ce), se2 = pk(-se, se), mse2 = pk(se, -se);
#pragma unroll
        for (int k = 0; k < 8; k++)
            crz1(re[k], im[k], ch2, se2, mse2);
        float cx = __ldg(gc + 7), sx = __ldg(gs + 7);
        float cxe = ctl ? cx : 1.0f, sxe = ctl ? sx : 0.0f;
        u64 cx2 = pk(cxe, cxe), x2P = pk(sxe, sxe), x2N = pk(-sxe, -sxe);
#pragma unroll
        for (int k = 0; k < 8; k++) {
            u64 swi = f2swap(im[k]);
            u64 swr = f2swap(re[k]);
            u64 m0 = f2mul(x2P, swi);
            u64 m1 = f2mul(x2N, swr);
            re[k] = f2fma(cx2, re[k], m0);
            im[k] = f2fma(cx2, im[k], m1);
        }
    }
    // ---- gate 4: (5,4). ctl = lane&2; CRZ sign by k&2; CRX pairs k^2
    {
        bool ctl = (lane & 2) != 0;
        float c = __ldg(gc + 8), s = __ldg(gs + 8);
        float ce = ctl ? c : 1.0f, se = ctl ? s : 0.0f;
        u64 ch2 = pk(ce, ce), sP = pk(se, se), sN = pk(-se, -se);
#pragma unroll
        for (int k = 0; k < 8; k++)
            crz1(re[k], im[k], ch2, (k & 2) ? sP : sN, (k & 2) ? sN : sP);
        float cx = __ldg(gc + 9), sx = __ldg(gs + 9);
        float cxe = ctl ? cx : 1.0f, sxe = ctl ? sx : 0.0f;
        u64 cx2 = pk(cxe, cxe), x2P = pk(sxe, sxe), x2N = pk(-sxe, -sxe);
        crx2(re[0], im[0], re[2], im[2], cx2, x2P, x2N);
        crx2(re[1], im[1], re[3], im[3], cx2, x2P, x2N);
        crx2(re[4], im[4], re[6], im[6], cx2, x2P, x2N);
        crx2(re[5], im[5], re[7], im[7], cx2, x2P, x2N);
    }
    // ---- gate 5: (7,6). ctl = within-pair hi (q7); tgt = k bit0 (q6)
    {
        float c = __ldg(gc + 10), s = __ldg(gs + 10);
        u64 ch2 = pk(1.0f, c), sP = pk(0.0f, s), sN = pk(0.0f, -s);
#pragma unroll
        for (int k = 0; k < 8; k++)
            crz1(re[k], im[k], ch2, (k & 1) ? sP : sN, (k & 1) ? sN : sP);
        float cx = __ldg(gc + 11), sx = __ldg(gs + 11);
        u64 cx2 = pk(1.0f, cx), x2P = pk(0.0f, sx), x2N = pk(0.0f, -sx);
        crx2(re[0], im[0], re[1], im[1], cx2, x2P, x2N);
        crx2(re[2], im[2], re[3], im[3], cx2, x2P, x2N);
        crx2(re[4], im[4], re[5], im[5], cx2, x2P, x2N);
        crx2(re[6], im[6], re[7], im[7], cx2, x2P, x2N);
    }
    // ---- gate 6: (6,4). ctl = k&1 (q6); tgt = k bit1 (q4); sign by k&2
    {
        float c = __ldg(gc + 12), s = __ldg(gs + 12);
        u64 ch2 = pk(c, c), sP = pk(s, s), sN = pk(-s, -s);
        crz1(re[1], im[1], ch2, sN, sP);
        crz1(re[3], im[3], ch2, sP, sN);
        crz1(re[5], im[5], ch2, sN, sP);
        crz1(re[7], im[7], ch2, sP, sN);
        float cx = __ldg(gc + 13), sx = __ldg(gs + 13);
        u64 cx2 = pk(cx, cx), x2P = pk(sx, sx), x2N = pk(-sx, -sx);
        crx2(re[1], im[1], re[3], im[3], cx2, x2P, x2N);
        crx2(re[5], im[5], re[7], im[7], cx2, x2P, x2N);
    }
    // ---- gate 7: (4,0). ctl = k&2 (q4); tgt = k bit2 (q0); sign by k&4
    {
        float c = __ldg(gc + 14), s = __ldg(gs + 14);
        u64 ch2 = pk(c, c), sP = pk(s, s), sN = pk(-s, -s);
        crz1(re[2], im[2], ch2, sN, sP);
        crz1(re[3], im[3], ch2, sN, sP);
        crz1(re[6], im[6], ch2, sP, sN);
        crz1(re[7], im[7], ch2, sP, sN);
        float cx = __ldg(gc + 15), sx = __ldg(gs + 15);
        u64 cx2 = pk(cx, cx), x2P = pk(sx, sx), x2N = pk(-sx, -sx);
        crx2(re[2], im[2], re[6], im[6], cx2, x2P, x2N);
        crx2(re[3], im[3], re[7], im[7], cx2, x2P, x2N);
    }

    // ---- measurement: z = P(q0=0) - P(q0=1); q0 = k bit2
    u64 accP = 0ULL, accN = 0ULL;   // bit pattern 0 == (0.f, 0.f)
#pragma unroll
    for (int k = 0; k < 8; k++) {
        if (k < 4) {
            accP = f2fma(re[k], re[k], accP);
            accP = f2fma(im[k], im[k], accP);
        } else {
            accN = f2fma(re[k], re[k], accN);
            accN = f2fma(im[k], im[k], accN);
        }
    }
    float pl, ph, nl, nh;
    upk(accP, pl, ph);
    upk(accN, nl, nh);
    float z = (pl + ph) - (nl + nh);
#pragma unroll
    for (int o = 16; o > 0; o >>= 1)
        z += __shfl_xor_sync(FULLMASK, z, o);

    if (lane == 0) {
        out[((b * 30 + r_ + 1) * 30 + (c_ + 1)) * 4 + ch] = (z + 1.0f) * 0.5f;
    }
}

extern "C" void kernel_launch(void* const* d_in, const int* in_sizes, int n_in,
                              void* d_out, int out_size) {
    const float* x  = (const float*)d_in[0];
    const float* qp = (const float*)d_in[1];
    if (n_in >= 2 && in_sizes[0] == 64) {
        const float* t = x; x = qp; qp = t;
    }
    float* out = (float*)d_out;

    prep_kernel<<<(28800 + 255) / 256, 256>>>(x, qp, out);
    sim_kernel<<<6272, 128>>>(out);
}

// round 8
// speedup vs baseline: 1.9037x; 1.9037x over previous
#include <cuda_runtime.h>
#include <cuda_bf16.h>

// ---------------------------------------------------------------------------
// Quanv3x3 9-qubit statevector sim, packed-f32x2, CRZ-folded init.
//
// One warp per sim (25088 sims). 512 amps = 16 complex/lane, stored as
// 8 x f32x2 packed pairs (pair dimension = qubit 7).
//
// Amp index bits:  lane b0=q8  b1=q5  b2=q3  b3=q1  b4=q2
//                  pair-lo/hi = q7;  k b0=q6  k b1=q4  k b2=q0
//
// CRZ gates of pairs (1,0), (3,2), (8,7), (5,4) are diagonal and commute
// backward past all earlier gates (disjoint qubits) -> folded into the
// initial-state phase. Remaining in-loop: 8 CRX + 4 CRZ.
//
// Codegen note (R5/R6 lesson): any launch_bounds reg ceiling < 128 makes
// ptxas rematerialize packed constants (+60% FMA work). Keep (256,2).
// ---------------------------------------------------------------------------

#define FULLMASK 0xffffffffu
typedef unsigned long long u64;

__device__ float g_s[7200];     // sin(pi * avg)  per (b,row,col)
__device__ float g_c[7200];     // cos(pi * avg)
__device__ float g_gc[64];      // cos(theta/2) per channel (4x16)
__device__ float g_gs[64];      // sin(theta/2)

__global__ void prep_kernel(const float* __restrict__ x,
                            const float* __restrict__ qp,
                            float* __restrict__ out) {
    int i = blockIdx.x * blockDim.x + threadIdx.x;
    if (i < 28800) out[i] = 0.0f;
    if (i < 7200) {
        const float* p = x + i * 3;
        float a = (p[0] + p[1] + p[2]) * (1.0f / 3.0f);
        float sv, cv;
        sincosf(3.14159265358979323846f * a, &sv, &cv);
        g_s[i] = sv;
        g_c[i] = cv;
    }
    if (i < 64) {
        float h = qp[i] * 0.5f;
        g_gc[i] = cosf(h);
        g_gs[i] = sinf(h);
    }
}

// ---- packed f32x2 primitives ----------------------------------------------
__device__ __forceinline__ u64 pk(float lo, float hi) {
    u64 r;
    asm("mov.b64 %0, {%1, %2};" : "=l"(r) : "f"(lo), "f"(hi));
    return r;
}
__device__ __forceinline__ void upk(u64 v, float& lo, float& hi) {
    asm("mov.b64 {%0, %1}, %2;" : "=f"(lo), "=f"(hi) : "l"(v));
}
__device__ __forceinline__ u64 f2fma(u64 a, u64 b, u64 c) {
    u64 d;
    asm("fma.rn.f32x2 %0, %1, %2, %3;" : "=l"(d) : "l"(a), "l"(b), "l"(c));
    return d;
}
__device__ __forceinline__ u64 f2mul(u64 a, u64 b) {
    u64 d;
    asm("mul.rn.f32x2 %0, %1, %2;" : "=l"(d) : "l"(a), "l"(b));
    return d;
}
__device__ __forceinline__ u64 f2swap(u64 v) {
    float lo, hi; upk(v, lo, hi); return pk(hi, lo);
}

// CRZ on one packed pair: nr = ch*r + (-se)*i ; ni = ch*i + se*r
__device__ __forceinline__ void crz1(u64& r, u64& i, u64 ch2, u64 se2, u64 mse2) {
    u64 tr = f2mul(mse2, i);
    u64 ti = f2mul(se2, r);
    r = f2fma(ch2, r, tr);
    i = f2fma(ch2, i, ti);
}

// CRX mixing packed pair A (target bit 0) with packed pair B (target bit 1).
__device__ __forceinline__ void crx2(u64& rA, u64& iA, u64& rB, u64& iB,
                                     u64 ch2, u64 sh2, u64 msh2) {
    u64 m0 = f2mul(sh2,  iB);
    u64 m1 = f2mul(msh2, rB);
    u64 m2 = f2mul(sh2,  iA);
    u64 m3 = f2mul(msh2, rA);
    rA = f2fma(ch2, rA, m0);
    iA = f2fma(ch2, iA, m1);
    rB = f2fma(ch2, rB, m2);
    iB = f2fma(ch2, iB, m3);
}

__global__ __launch_bounds__(256, 2) void sim_kernel(float* __restrict__ out) {
    int gwarp = (blockIdx.x * blockDim.x + threadIdx.x) >> 5;
    int lane = threadIdx.x & 31;

    int b   = gwarp / 3136;
    int rem = gwarp - b * 3136;
    int ch  = rem / 784;
    int pos = rem - ch * 784;
    int r_  = pos / 28;
    int c_  = pos - r_ * 28;

    // ---- patch angles: cq = sin(pi*p), sq = -cos(pi*p)  (precomputed tables)
    float sv = 0.0f, cv = 0.0f;
    if (lane < 9) {
        int dr = lane / 3;
        int dc = lane - dr * 3;
        int idx = b * 900 + (r_ + dr) * 30 + (c_ + dc);
        sv = __ldg(g_s + idx);
        cv = __ldg(g_c + idx);
    }
    float cq[9], sq[9];
#pragma unroll
    for (int q = 0; q < 9; q++) {
        cq[q] = __shfl_sync(FULLMASK, sv, q);
        sq[q] = -__shfl_sync(FULLMASK, cv, q);
    }

    const float* gc = g_gc + ch * 16;
    const float* gs = g_gs + ch * 16;

    // ---- folded CRZ phases (gates g0, g1, g3, g4) -------------------------
    float c0 = __ldg(gc + 0), s0 = __ldg(gs + 0);   // g0 CRZ(1,0)
    float c2g = __ldg(gc + 2), s2g = __ldg(gs + 2); // g1 CRZ(3,2)
    float c6g = __ldg(gc + 6), s6g = __ldg(gs + 6); // g3 CRZ(8,7)
    float c8g = __ldg(gc + 8), s8g = __ldg(gs + 8); // g4 CRZ(5,4)

    // w = (-i)^popc(lane)
    int lk = __popc(lane & 31) & 3;
    float wr = (lk == 0) ? 1.0f : ((lk == 2) ? -1.0f : 0.0f);
    float wi = (lk == 3) ? 1.0f : ((lk == 1) ? -1.0f : 0.0f);

    // pA: g1 CRZ, ctrl=lane&4, tgt=lane&16 (pure lane phase)
    bool aCtl = (lane & 4) != 0;
    float pAr = aCtl ? c2g : 1.0f;
    float pAi = aCtl ? ((lane & 16) ? s2g : -s2g) : 0.0f;
    float wpr = wr * pAr - wi * pAi;   // w' = w * pA
    float wpi = wr * pAi + wi * pAr;

    // S (packed over slot): g3 CRZ (ctrl=lane&1, tgt=slot) * (-i)^slot
    bool g3c_ = (lane & 1) != 0;
    float e3c = g3c_ ? c6g : 1.0f, e3s = g3c_ ? s6g : 0.0f;
    // lo = (e3c, -e3s);  hi = (-i)*(e3c, +e3s) = (e3s, -e3c)
    u64 Sre = pk(e3c, e3s);
    u64 Sim = pk(-e3s, -e3c);

    // T = w' * S
    u64 wpr2 = pk(wpr, wpr), wpi2 = pk(wpi, wpi), nwpi2 = pk(-wpi, -wpi);
    u64 Tre = f2fma(wpr2, Sre, f2mul(nwpi2, Sim));
    u64 Tim = f2fma(wpr2, Sim, f2mul(wpi2, Sre));

    // qq2 (k bit1 / q4, gate g4): k2=0 -> (e4c,-e4s); k2=1 -> (-i)*(e4c,+e4s)
    bool g4c_ = (lane & 2) != 0;
    float e4c = g4c_ ? c8g : 1.0f, e4s = g4c_ ? s8g : 0.0f;
    float q2r[2] = { e4c,  e4s };
    float q2i[2] = { -e4s, -e4c };
    // qq4 (k bit2 / q0, gate g0): same pattern with ctrl lane&8
    bool g0c_ = (lane & 8) != 0;
    float e0c = g0c_ ? c0 : 1.0f, e0s = g0c_ ? s0 : 0.0f;
    float q4r[2] = { e0c,  e0s };
    float q4i[2] = { -e0s, -e0c };

    // U[idx] = T * (qq2*qq4), idx = k2bit + 2*k4bit
    u64 Ure[4], Uim[4];
#pragma unroll
    for (int i4 = 0; i4 < 2; i4++) {
#pragma unroll
        for (int i2 = 0; i2 < 2; i2++) {
            float qr = q2r[i2] * q4r[i4] - q2i[i2] * q4i[i4];
            float qi = q2r[i2] * q4i[i4] + q2i[i2] * q4r[i4];
            u64 qr2 = pk(qr, qr), qi2 = pk(qi, qi), nqi2 = pk(-qi, -qi);
            Ure[i2 + 2 * i4] = f2fma(qr2, Tre, f2mul(nqi2, Tim));
            Uim[i2 + 2 * i4] = f2fma(qr2, Tim, f2mul(qi2, Tre));
        }
    }

    // ---- initial state with folded phases ---------------------------------
    float lr = ((lane & 1)  ? sq[8] : cq[8]) *
               ((lane & 2)  ? sq[5] : cq[5]) *
               ((lane & 4)  ? sq[3] : cq[3]) *
               ((lane & 8)  ? sq[1] : cq[1]) *
               ((lane & 16) ? sq[2] : cq[2]);
    u64 cs7  = pk(cq[7], sq[7]);
    u64 ncs7 = pk(-cq[7], -sq[7]);

    u64 re[8], im[8];
#pragma unroll
    for (int k = 0; k < 8; k++) {
        float rr = lr * ((k & 1) ? sq[6] : cq[6]) *
                        ((k & 2) ? sq[4] : cq[4]) *
                        ((k & 4) ? sq[0] : cq[0]);
        u64 rr2 = pk(rr, rr);
        int idx = ((k >> 1) & 1) + 2 * ((k >> 2) & 1);
        if (!(k & 1)) {
            u64 R2 = f2mul(rr2, cs7);
            re[k] = f2mul(R2, Ure[idx]);
            im[k] = f2mul(R2, Uim[idx]);
        } else {
            // extra (-i) for k bit0: (re,im) <- (im, -re) of the even formula
            u64 R2  = f2mul(rr2, cs7);
            u64 Rn2 = f2mul(rr2, ncs7);
            re[k] = f2mul(R2,  Uim[idx]);
            im[k] = f2mul(Rn2, Ure[idx]);
        }
    }

    // ---- gate 0: (1,0) CRX only (CRZ folded). ctl = lane&8; pairs k^4
    {
        bool ctl = (lane & 8) != 0;
        float cx = __ldg(gc + 1), sx = __ldg(gs + 1);
        float cxe = ctl ? cx : 1.0f, sxe = ctl ? sx : 0.0f;
        u64 cx2 = pk(cxe, cxe), x2P = pk(sxe, sxe), x2N = pk(-sxe, -sxe);
        crx2(re[0], im[0], re[4], im[4], cx2, x2P, x2N);
        crx2(re[1], im[1], re[5], im[5], cx2, x2P, x2N);
        crx2(re[2], im[2], re[6], im[6], cx2, x2P, x2N);
        crx2(re[3], im[3], re[7], im[7], cx2, x2P, x2N);
    }
    // ---- gate 1: (3,2) CRX only (CRZ folded). ctl = lane&4; cross-lane xor16
    {
        bool ctl = (lane & 4) != 0;
        float cx = __ldg(gc + 3), sx = __ldg(gs + 3);
        float cxe = ctl ? cx : 1.0f, sxe = ctl ? sx : 0.0f;
        u64 cx2 = pk(cxe, cxe), x2P = pk(sxe, sxe), x2N = pk(-sxe, -sxe);
#pragma unroll
        for (int k = 0; k < 8; k++) {
            u64 orr = __shfl_xor_sync(FULLMASK, re[k], 16);
            u64 oii = __shfl_xor_sync(FULLMASK, im[k], 16);
            u64 m0 = f2mul(x2P, oii);
            u64 m1 = f2mul(x2N, orr);
            re[k] = f2fma(cx2, re[k], m0);
            im[k] = f2fma(cx2, im[k], m1);
        }
    }
    // ---- gate 2: (2,0). ctl = lane&16; CRZ sign by k&4; CRX pairs k^4
    {
        bool ctl = (lane & 16) != 0;
        float c = __ldg(gc + 4), s = __ldg(gs + 4);
        float ce = ctl ? c : 1.0f, se = ctl ? s : 0.0f;
        u64 ch2 = pk(ce, ce), sP = pk(se, se), sN = pk(-se, -se);
#pragma unroll
        for (int k = 0; k < 8; k++)
            crz1(re[k], im[k], ch2, (k & 4) ? sP : sN, (k & 4) ? sN : sP);
        float cx = __ldg(gc + 5), sx = __ldg(gs + 5);
        float cxe = ctl ? cx : 1.0f, sxe = ctl ? sx : 0.0f;
        u64 cx2 = pk(cxe, cxe), x2P = pk(sxe, sxe), x2N = pk(-sxe, -sxe);
        crx2(re[0], im[0], re[4], im[4], cx2, x2P, x2N);
        crx2(re[1], im[1], re[5], im[5], cx2, x2P, x2N);
        crx2(re[2], im[2], re[6], im[6], cx2, x2P, x2N);
        crx2(re[3], im[3], re[7], im[7], cx2, x2P, x2N);
    }
    // ---- gate 3: (8,7) CRX only (CRZ folded). ctl = lane&1; tgt = pair bit
    {
        bool ctl = (lane & 1) != 0;
        float cx = __ldg(gc + 7), sx = __ldg(gs + 7);
        float cxe = ctl ? cx : 1.0f, sxe = ctl ? sx : 0.0f;
        u64 cx2 = pk(cxe, cxe), x2P = pk(sxe, sxe), x2N = pk(-sxe, -sxe);
#pragma unroll
        for (int k = 0; k < 8; k++) {
            u64 swi = f2swap(im[k]);
            u64 swr = f2swap(re[k]);
            u64 m0 = f2mul(x2P, swi);
            u64 m1 = f2mul(x2N, swr);
            re[k] = f2fma(cx2, re[k], m0);
            im[k] = f2fma(cx2, im[k], m1);
        }
    }
    // ---- gate 4: (5,4) CRX only (CRZ folded). ctl = lane&2; pairs k^2
    {
        bool ctl = (lane & 2) != 0;
        float cx = __ldg(gc + 9), sx = __ldg(gs + 9);
        float cxe = ctl ? cx : 1.0f, sxe = ctl ? sx : 0.0f;
        u64 cx2 = pk(cxe, cxe), x2P = pk(sxe, sxe), x2N = pk(-sxe, -sxe);
        crx2(re[0], im[0], re[2], im[2], cx2, x2P, x2N);
        crx2(re[1], im[1], re[3], im[3], cx2, x2P, x2N);
        crx2(re[4], im[4], re[6], im[6], cx2, x2P, x2N);
        crx2(re[5], im[5], re[7], im[7], cx2, x2P, x2N);
    }
    // ---- gate 5: (7,6). ctl = within-pair hi (q7); tgt = k bit0 (q6)
    {
        float c = __ldg(gc + 10), s = __ldg(gs + 10);
        u64 ch2 = pk(1.0f, c), sP = pk(0.0f, s), sN = pk(0.0f, -s);
#pragma unroll
        for (int k = 0; k < 8; k++)
            crz1(re[k], im[k], ch2, (k & 1) ? sP : sN, (k & 1) ? sN : sP);
        float cx = __ldg(gc + 11), sx = __ldg(gs + 11);
        u64 cx2 = pk(1.0f, cx), x2P = pk(0.0f, sx), x2N = pk(0.0f, -sx);
        crx2(re[0], im[0], re[1], im[1], cx2, x2P, x2N);
        crx2(re[2], im[2], re[3], im[3], cx2, x2P, x2N);
        crx2(re[4], im[4], re[5], im[5], cx2, x2P, x2N);
        crx2(re[6], im[6], re[7], im[7], cx2, x2P, x2N);
    }
    // ---- gate 6: (6,4). ctl = k&1 (q6); tgt = k bit1 (q4); sign by k&2
    {
        float c = __ldg(gc + 12), s = __ldg(gs + 12);
        u64 ch2 = pk(c, c), sP = pk(s, s), sN = pk(-s, -s);
        crz1(re[1], im[1], ch2, sN, sP);
        crz1(re[3], im[3], ch2, sP, sN);
        crz1(re[5], im[5], ch2, sN, sP);
        crz1(re[7], im[7], ch2, sP, sN);
        float cx = __ldg(gc + 13), sx = __ldg(gs + 13);
        u64 cx2 = pk(cx, cx), x2P = pk(sx, sx), x2N = pk(-sx, -sx);
        crx2(re[1], im[1], re[3], im[3], cx2, x2P, x2N);
        crx2(re[5], im[5], re[7], im[7], cx2, x2P, x2N);
    }
    // ---- gate 7: (4,0). ctl = k&2 (q4); tgt = k bit2 (q0); sign by k&4
    {
        float c = __ldg(gc + 14), s = __ldg(gs + 14);
        u64 ch2 = pk(c, c), sP = pk(s, s), sN = pk(-s, -s);
        crz1(re[2], im[2], ch2, sN, sP);
        crz1(re[3], im[3], ch2, sN, sP);
        crz1(re[6], im[6], ch2, sP, sN);
        crz1(re[7], im[7], ch2, sP, sN);
        float cx = __ldg(gc + 15), sx = __ldg(gs + 15);
        u64 cx2 = pk(cx, cx), x2P = pk(sx, sx), x2N = pk(-sx, -sx);
        crx2(re[2], im[2], re[6], im[6], cx2, x2P, x2N);
        crx2(re[3], im[3], re[7], im[7], cx2, x2P, x2N);
    }

    // ---- measurement: z = P(q0=0) - P(q0=1); q0 = k bit2
    u64 accP = 0ULL, accN = 0ULL;   // bit pattern 0 == (0.f, 0.f)
#pragma unroll
    for (int k = 0; k < 8; k++) {
        if (k < 4) {
            accP = f2fma(re[k], re[k], accP);
            accP = f2fma(im[k], im[k], accP);
        } else {
            accN = f2fma(re[k], re[k], accN);
            accN = f2fma(im[k], im[k], accN);
        }
    }
    float pl, ph, nl, nh;
    upk(accP, pl, ph);
    upk(accN, nl, nh);
    float z = (pl + ph) - (nl + nh);
#pragma unroll
    for (int o = 16; o > 0; o >>= 1)
        z += __shfl_xor_sync(FULLMASK, z, o);

    if (lane == 0) {
        out[((b * 30 + r_ + 1) * 30 + (c_ + 1)) * 4 + ch] = (z + 1.0f) * 0.5f;
    }
}

extern "C" void kernel_launch(void* const* d_in, const int* in_sizes, int n_in,
                              void* d_out, int out_size) {
    const float* x  = (const float*)d_in[0];
    const float* qp = (const float*)d_in[1];
    if (n_in >= 2 && in_sizes[0] == 64) {
        const float* t = x; x = qp; qp = t;
    }
    float* out = (float*)d_out;

    prep_kernel<<<(28800 + 255) / 256, 256>>>(x, qp, out);
    sim_kernel<<<3136, 256>>>(out);
}